// round 4
// baseline (speedup 1.0000x reference)
#include <cuda_runtime.h>
#include <math.h>
#include <float.h>

#define BB 16384
#define DD 4096
#define NE 64
#define ROWS_PER_EPI_BLOCK 8
#define EPI_BLOCKS (BB / ROWS_PER_EPI_BLOCK)   // 2048

// Scratch: fused logits [B, 128] (cols 0..63 = clean, 64..127 = noise-pre-softplus)
__device__ float g_logits[(size_t)BB * 128];
// Per-epilogue-block partial load sums (deterministic reduction, no atomics)
__device__ float g_partial[EPI_BLOCKS * NE];

// ---------------------------------------------------------------------------
// GEMM: logits[b, 0:64] = x @ w_gate ; logits[b, 64:128] = x @ w_noise
// 256 threads/block, tile 64 rows x 128 cols, K-chunk 32, 4x8 per thread.
// Chunk sums folded with Kahan compensation -> total rounding ~2e-7.
// ---------------------------------------------------------------------------
__global__ __launch_bounds__(256) void gemm_kernel(const float* __restrict__ x,
                                                   const float* __restrict__ wg,
                                                   const float* __restrict__ wn) {
    __shared__ float xs[32][64];    // [k][row]
    __shared__ float ws[32][128];   // [k][col]
    const int t = threadIdx.x;
    const int rowbase = blockIdx.x * 64;
    const int tx = t & 15, ty = t >> 4;
    const int r0 = ty * 4, c0 = tx * 8;

    float acc[4][8], cmp[4][8];
#pragma unroll
    for (int r = 0; r < 4; r++)
#pragma unroll
        for (int c = 0; c < 8; c++) { acc[r][c] = 0.f; cmp[r][c] = 0.f; }

    for (int k0 = 0; k0 < DD; k0 += 32) {
        // load x tile (transposed into smem): 64 rows x 32 k
#pragma unroll
        for (int i = 0; i < 2; i++) {
            int v = t + 256 * i;
            int row = v >> 3, c4 = v & 7;
            float4 d = *(const float4*)(x + (size_t)(rowbase + row) * DD + k0 + c4 * 4);
            xs[c4 * 4 + 0][row] = d.x;
            xs[c4 * 4 + 1][row] = d.y;
            xs[c4 * 4 + 2][row] = d.z;
            xs[c4 * 4 + 3][row] = d.w;
        }
        // load w tile: 32 k x 128 cols (gate | noise)
#pragma unroll
        for (int i = 0; i < 4; i++) {
            int v = t + 256 * i;
            int k = v >> 5, c = (v & 31) * 4;
            float4 d;
            if (c < 64) d = *(const float4*)(wg + (size_t)(k0 + k) * 64 + c);
            else        d = *(const float4*)(wn + (size_t)(k0 + k) * 64 + (c - 64));
            *(float4*)&ws[k][c] = d;
        }
        __syncthreads();

        float cacc[4][8];
#pragma unroll
        for (int r = 0; r < 4; r++)
#pragma unroll
            for (int c = 0; c < 8; c++) cacc[r][c] = 0.f;

#pragma unroll
        for (int kk = 0; kk < 32; kk++) {
            float4 xv = *(const float4*)&xs[kk][r0];
            float4 w0 = *(const float4*)&ws[kk][c0];
            float4 w1 = *(const float4*)&ws[kk][c0 + 4];
            float xr[4] = {xv.x, xv.y, xv.z, xv.w};
            float wc[8] = {w0.x, w0.y, w0.z, w0.w, w1.x, w1.y, w1.z, w1.w};
#pragma unroll
            for (int r = 0; r < 4; r++)
#pragma unroll
                for (int c = 0; c < 8; c++)
                    cacc[r][c] = fmaf(xr[r], wc[c], cacc[r][c]);
        }
        // Kahan fold of the chunk sum into the main accumulator
#pragma unroll
        for (int r = 0; r < 4; r++)
#pragma unroll
            for (int c = 0; c < 8; c++) {
                float y = cacc[r][c] - cmp[r][c];
                float tt = acc[r][c] + y;
                cmp[r][c] = (tt - acc[r][c]) - y;
                acc[r][c] = tt;
            }
        __syncthreads();
    }

#pragma unroll
    for (int r = 0; r < 4; r++) {
        float* o = &g_logits[(size_t)(rowbase + r0 + r) * 128 + c0];
        *(float4*)(o + 0) = make_float4(acc[r][0], acc[r][1], acc[r][2], acc[r][3]);
        *(float4*)(o + 4) = make_float4(acc[r][4], acc[r][5], acc[r][6], acc[r][7]);
    }
}

// ---------------------------------------------------------------------------
// Epilogue: one warp per row. lane holds experts {lane, lane+32}.
// Discrete decisions (top-9 selection) in fp64: ordering == exact ordering.
// ---------------------------------------------------------------------------
__device__ __forceinline__ double softplus_d(double v) {
    return fmax(v, 0.0) + log1p(exp(-fabs(v)));
}

__global__ __launch_bounds__(256) void epilogue_kernel(const float* __restrict__ noise,
                                                       float* __restrict__ out_gates) {
    __shared__ float loadsm[ROWS_PER_EPI_BLOCK][NE];
    const int t = threadIdx.x;
    const int warp = t >> 5, lane = t & 31;
    const int row = blockIdx.x * ROWS_PER_EPI_BLOCK + warp;

    const float* Lr = &g_logits[(size_t)row * 128];
    const int eA = lane, eB = lane + 32;

    float cleanA = Lr[eA], cleanB = Lr[eB];
    double stdA_d = softplus_d((double)Lr[64 + eA]) + 0.01;
    double stdB_d = softplus_d((double)Lr[64 + eB]) + 0.01;
    float nzA = noise[(size_t)row * NE + eA];
    float nzB = noise[(size_t)row * NE + eB];
    double noisyA_d = (double)cleanA + (double)nzA * stdA_d;
    double noisyB_d = (double)cleanB + (double)nzB * stdB_d;
    float stdA = (float)stdA_d, stdB = (float)stdB_d;
    float noisyA = (float)noisyA_d, noisyB = (float)noisyB_d;

    // ---- top-9 selection by fp64 noisy logit (desc; tie -> lower index) ----
    double vA = noisyA_d, vB = noisyB_d;
    double topl[9];
    int    topi[9];
#pragma unroll
    for (int it = 0; it < 9; it++) {
        double bv; int bi;
        if (vB > vA) { bv = vB; bi = eB; } else { bv = vA; bi = eA; }
#pragma unroll
        for (int off = 16; off; off >>= 1) {
            double ov = __shfl_xor_sync(0xffffffffu, bv, off);
            int    oi = __shfl_xor_sync(0xffffffffu, bi, off);
            if (ov > bv || (ov == bv && oi < bi)) { bv = ov; bi = oi; }
        }
        topl[it] = bv; topi[it] = bi;
        if (bi == eA) vA = -DBL_MAX;
        if (bi == eB) vB = -DBL_MAX;
    }

    // ---- softmax denominator over 64 experts (fp32 values are fine) ----
    float m = (float)topl[0];
    float s = expf(noisyA - m) + expf(noisyB - m);
#pragma unroll
    for (int off = 16; off; off >>= 1) s += __shfl_xor_sync(0xffffffffu, s, off);

    // probs of the selected 9
    float p[9];
#pragma unroll
    for (int i = 0; i < 9; i++) p[i] = expf((float)(topl[i]) - m) / s;

    // gates = softmax over top-8 prob values (reference semantics)
    float gs = 0.f;
#pragma unroll
    for (int i = 0; i < 8; i++) gs += expf(p[i] - p[0]);
    float gA = 0.f, gB = 0.f;
#pragma unroll
    for (int i = 0; i < 8; i++) {
        float g = expf(p[i] - p[0]) / gs;
        if (topi[i] == eA) gA = g;
        if (topi[i] == eB) gB = g;
    }
    out_gates[(size_t)row * NE + eA] = gA;
    out_gates[(size_t)row * NE + eB] = gB;

    // ---- load: thresholds are PROB values compared vs noisy LOGITS (faithful) ----
    float thr_in  = p[8];
    float thr_out = p[7];
    const float INV_SQRT2 = 0.70710678118654752440f;
    float tA = (noisyA > thr_in) ? thr_in : thr_out;
    float tB = (noisyB > thr_in) ? thr_in : thr_out;
    float lA = 0.5f * (1.f + erff(((cleanA - tA) / stdA) * INV_SQRT2));
    float lB = 0.5f * (1.f + erff(((cleanB - tB) / stdB) * INV_SQRT2));
    loadsm[warp][eA] = lA;
    loadsm[warp][eB] = lB;
    __syncthreads();

    if (t < NE) {
        float acc2 = 0.f;
#pragma unroll
        for (int w = 0; w < ROWS_PER_EPI_BLOCK; w++) acc2 += loadsm[w][t];
        g_partial[(size_t)blockIdx.x * NE + t] = acc2;
    }
}

// Deterministic final reduction of load partials: 1024 threads,
// 16 segments x 64 experts, fixed-order tree combine.
__global__ __launch_bounds__(1024) void reduce_load_kernel(float* __restrict__ out_load) {
    __shared__ float seg[16][NE];
    const int e = threadIdx.x & 63;
    const int sgi = threadIdx.x >> 6;          // 0..15
    const int per = EPI_BLOCKS / 16;           // 128
    float acc = 0.f;
#pragma unroll 8
    for (int b = sgi * per; b < (sgi + 1) * per; b++)
        acc += g_partial[(size_t)b * NE + e];
    seg[sgi][e] = acc;
    __syncthreads();
    if (threadIdx.x < NE) {
        float a = 0.f;
#pragma unroll
        for (int i = 0; i < 16; i++) a += seg[i][threadIdx.x];
        out_load[threadIdx.x] = a;
    }
}

extern "C" void kernel_launch(void* const* d_in, const int* in_sizes, int n_in,
                              void* d_out, int out_size) {
    const float* x     = (const float*)d_in[0];
    const float* wg    = (const float*)d_in[1];
    const float* wn    = (const float*)d_in[2];
    const float* noise = (const float*)d_in[3];
    float* out_gates = (float*)d_out;
    float* out_load  = (float*)d_out + (size_t)BB * NE;

    gemm_kernel<<<BB / 64, 256>>>(x, wg, wn);
    epilogue_kernel<<<EPI_BLOCKS, 256>>>(noise, out_gates);
    reduce_load_kernel<<<1, 1024>>>(out_load);
}

// round 5
// speedup vs baseline: 1.0035x; 1.0035x over previous
#include <cuda_runtime.h>
#include <math.h>
#include <float.h>

#define BB 16384
#define DD 4096
#define NE 64
#define ROWS_PER_EPI_BLOCK 8
#define EPI_BLOCKS (BB / ROWS_PER_EPI_BLOCK)   // 2048

// Scratch: fused logits [B, 128] (cols 0..63 = clean, 64..127 = noise-pre-softplus)
__device__ float g_logits[(size_t)BB * 128];
// Per-epilogue-block partial load sums (deterministic reduction, no atomics)
__device__ float g_partial[EPI_BLOCKS * NE];

// ---------------------------------------------------------------------------
// GEMM: logits[b, 0:64] = x @ w_gate ; logits[b, 64:128] = x @ w_noise
// 256 threads/block, tile 64 rows x 128 cols, K-chunk 32, 4x8 per thread.
// Chunk sums folded with Kahan compensation -> total rounding ~2e-7.
// ---------------------------------------------------------------------------
__global__ __launch_bounds__(256) void gemm_kernel(const float* __restrict__ x,
                                                   const float* __restrict__ wg,
                                                   const float* __restrict__ wn) {
    __shared__ float xs[32][64];    // [k][row]
    __shared__ float ws[32][128];   // [k][col]
    const int t = threadIdx.x;
    const int rowbase = blockIdx.x * 64;
    const int tx = t & 15, ty = t >> 4;
    const int r0 = ty * 4, c0 = tx * 8;

    float acc[4][8], cmp[4][8];
#pragma unroll
    for (int r = 0; r < 4; r++)
#pragma unroll
        for (int c = 0; c < 8; c++) { acc[r][c] = 0.f; cmp[r][c] = 0.f; }

    for (int k0 = 0; k0 < DD; k0 += 32) {
        // load x tile (transposed into smem): 64 rows x 32 k
#pragma unroll
        for (int i = 0; i < 2; i++) {
            int v = t + 256 * i;
            int row = v >> 3, c4 = v & 7;
            float4 d = *(const float4*)(x + (size_t)(rowbase + row) * DD + k0 + c4 * 4);
            xs[c4 * 4 + 0][row] = d.x;
            xs[c4 * 4 + 1][row] = d.y;
            xs[c4 * 4 + 2][row] = d.z;
            xs[c4 * 4 + 3][row] = d.w;
        }
        // load w tile: 32 k x 128 cols (gate | noise)
#pragma unroll
        for (int i = 0; i < 4; i++) {
            int v = t + 256 * i;
            int k = v >> 5, c = (v & 31) * 4;
            float4 d;
            if (c < 64) d = *(const float4*)(wg + (size_t)(k0 + k) * 64 + c);
            else        d = *(const float4*)(wn + (size_t)(k0 + k) * 64 + (c - 64));
            *(float4*)&ws[k][c] = d;
        }
        __syncthreads();

        float cacc[4][8];
#pragma unroll
        for (int r = 0; r < 4; r++)
#pragma unroll
            for (int c = 0; c < 8; c++) cacc[r][c] = 0.f;

#pragma unroll
        for (int kk = 0; kk < 32; kk++) {
            float4 xv = *(const float4*)&xs[kk][r0];
            float4 w0 = *(const float4*)&ws[kk][c0];
            float4 w1 = *(const float4*)&ws[kk][c0 + 4];
            float xr[4] = {xv.x, xv.y, xv.z, xv.w};
            float wc[8] = {w0.x, w0.y, w0.z, w0.w, w1.x, w1.y, w1.z, w1.w};
#pragma unroll
            for (int r = 0; r < 4; r++)
#pragma unroll
                for (int c = 0; c < 8; c++)
                    cacc[r][c] = fmaf(xr[r], wc[c], cacc[r][c]);
        }
        // Kahan fold of the chunk sum into the main accumulator
#pragma unroll
        for (int r = 0; r < 4; r++)
#pragma unroll
            for (int c = 0; c < 8; c++) {
                float y = cacc[r][c] - cmp[r][c];
                float tt = acc[r][c] + y;
                cmp[r][c] = (tt - acc[r][c]) - y;
                acc[r][c] = tt;
            }
        __syncthreads();
    }

#pragma unroll
    for (int r = 0; r < 4; r++) {
        float* o = &g_logits[(size_t)(rowbase + r0 + r) * 128 + c0];
        *(float4*)(o + 0) = make_float4(acc[r][0], acc[r][1], acc[r][2], acc[r][3]);
        *(float4*)(o + 4) = make_float4(acc[r][4], acc[r][5], acc[r][6], acc[r][7]);
    }
}

// ---------------------------------------------------------------------------
// Epilogue: one warp per row. lane holds experts {lane, lane+32}.
// Discrete decisions (top-9 selection) in fp64: ordering == exact ordering.
// ---------------------------------------------------------------------------
__device__ __forceinline__ double softplus_d(double v) {
    return fmax(v, 0.0) + log1p(exp(-fabs(v)));
}

__global__ __launch_bounds__(256) void epilogue_kernel(const float* __restrict__ noise,
                                                       float* __restrict__ out_gates) {
    __shared__ float loadsm[ROWS_PER_EPI_BLOCK][NE];
    const int t = threadIdx.x;
    const int warp = t >> 5, lane = t & 31;
    const int row = blockIdx.x * ROWS_PER_EPI_BLOCK + warp;

    const float* Lr = &g_logits[(size_t)row * 128];
    const int eA = lane, eB = lane + 32;

    float cleanA = Lr[eA], cleanB = Lr[eB];
    double stdA_d = softplus_d((double)Lr[64 + eA]) + 0.01;
    double stdB_d = softplus_d((double)Lr[64 + eB]) + 0.01;
    float nzA = noise[(size_t)row * NE + eA];
    float nzB = noise[(size_t)row * NE + eB];
    double noisyA_d = (double)cleanA + (double)nzA * stdA_d;
    double noisyB_d = (double)cleanB + (double)nzB * stdB_d;
    float stdA = (float)stdA_d, stdB = (float)stdB_d;
    float noisyA = (float)noisyA_d, noisyB = (float)noisyB_d;

    // ---- top-9 selection by fp64 noisy logit (desc; tie -> lower index) ----
    double vA = noisyA_d, vB = noisyB_d;
    double topl[9];
    int    topi[9];
#pragma unroll
    for (int it = 0; it < 9; it++) {
        double bv; int bi;
        if (vB > vA) { bv = vB; bi = eB; } else { bv = vA; bi = eA; }
#pragma unroll
        for (int off = 16; off; off >>= 1) {
            double ov = __shfl_xor_sync(0xffffffffu, bv, off);
            int    oi = __shfl_xor_sync(0xffffffffu, bi, off);
            if (ov > bv || (ov == bv && oi < bi)) { bv = ov; bi = oi; }
        }
        topl[it] = bv; topi[it] = bi;
        if (bi == eA) vA = -DBL_MAX;
        if (bi == eB) vB = -DBL_MAX;
    }

    // ---- softmax denominator over 64 experts (fp32 values are fine) ----
    float m = (float)topl[0];
    float s = expf(noisyA - m) + expf(noisyB - m);
#pragma unroll
    for (int off = 16; off; off >>= 1) s += __shfl_xor_sync(0xffffffffu, s, off);

    // probs of the selected 9
    float p[9];
#pragma unroll
    for (int i = 0; i < 9; i++) p[i] = expf((float)(topl[i]) - m) / s;

    // gates = softmax over top-8 prob values (reference semantics)
    float gs = 0.f;
#pragma unroll
    for (int i = 0; i < 8; i++) gs += expf(p[i] - p[0]);
    float gA = 0.f, gB = 0.f;
#pragma unroll
    for (int i = 0; i < 8; i++) {
        float g = expf(p[i] - p[0]) / gs;
        if (topi[i] == eA) gA = g;
        if (topi[i] == eB) gB = g;
    }
    out_gates[(size_t)row * NE + eA] = gA;
    out_gates[(size_t)row * NE + eB] = gB;

    // ---- load: thresholds are PROB values compared vs noisy LOGITS (faithful) ----
    float thr_in  = p[8];
    float thr_out = p[7];
    const float INV_SQRT2 = 0.70710678118654752440f;
    float tA = (noisyA > thr_in) ? thr_in : thr_out;
    float tB = (noisyB > thr_in) ? thr_in : thr_out;
    float lA = 0.5f * (1.f + erff(((cleanA - tA) / stdA) * INV_SQRT2));
    float lB = 0.5f * (1.f + erff(((cleanB - tB) / stdB) * INV_SQRT2));
    loadsm[warp][eA] = lA;
    loadsm[warp][eB] = lB;
    __syncthreads();

    if (t < NE) {
        float acc2 = 0.f;
#pragma unroll
        for (int w = 0; w < ROWS_PER_EPI_BLOCK; w++) acc2 += loadsm[w][t];
        g_partial[(size_t)blockIdx.x * NE + t] = acc2;
    }
}

// Deterministic final reduction of load partials: 1024 threads,
// 16 segments x 64 experts, fixed-order tree combine.
__global__ __launch_bounds__(1024) void reduce_load_kernel(float* __restrict__ out_load) {
    __shared__ float seg[16][NE];
    const int e = threadIdx.x & 63;
    const int sgi = threadIdx.x >> 6;          // 0..15
    const int per = EPI_BLOCKS / 16;           // 128
    float acc = 0.f;
#pragma unroll 8
    for (int b = sgi * per; b < (sgi + 1) * per; b++)
        acc += g_partial[(size_t)b * NE + e];
    seg[sgi][e] = acc;
    __syncthreads();
    if (threadIdx.x < NE) {
        float a = 0.f;
#pragma unroll
        for (int i = 0; i < 16; i++) a += seg[i][threadIdx.x];
        out_load[threadIdx.x] = a;
    }
}

extern "C" void kernel_launch(void* const* d_in, const int* in_sizes, int n_in,
                              void* d_out, int out_size) {
    const float* x     = (const float*)d_in[0];
    const float* wg    = (const float*)d_in[1];
    const float* wn    = (const float*)d_in[2];
    const float* noise = (const float*)d_in[3];
    float* out_gates = (float*)d_out;
    float* out_load  = (float*)d_out + (size_t)BB * NE;

    gemm_kernel<<<BB / 64, 256>>>(x, wg, wn);
    epilogue_kernel<<<EPI_BLOCKS, 256>>>(noise, out_gates);
    reduce_load_kernel<<<1, 1024>>>(out_load);
}